// round 2
// baseline (speedup 1.0000x reference)
#include <cuda_runtime.h>
#include <cuda_bf16.h>

// Problem constants
#define BB 2
#define LL 1024
#define CA 512
#define CS 384
#define CZ 64
#define HH 16
#define DD 32
#define MM (BB*LL)          // 2048 rows
#define SCALE 0.17677669529663687f  // 1/sqrt(32)

// -------------------- device scratch (no cudaMalloc allowed) --------------------
__device__ __align__(16) float g_s_ln[MM*CS];
__device__ __align__(16) float g_a_ln[MM*CA];
__device__ __align__(16) float g_anorm[MM*CA];
__device__ __align__(16) float g_glast[MM*CA];
__device__ __align__(16) float g_q[MM*CA];   // [b][h][l][d]
__device__ __align__(16) float g_k[MM*CA];
__device__ __align__(16) float g_v[MM*CA];
__device__ __align__(16) float g_g[MM*CA];   // pre-sigmoid gate, [m][c]
__device__ __align__(16) float g_ao[MM*CA];  // attention out, [b][l][h*32+d]
__device__ __align__(16) float g_bias[(size_t)BB*HH*LL*LL]; // 134MB

__device__ __forceinline__ float sigm(float x){ return 1.f/(1.f+__expf(-x)); }

// -------------------- kernel 1: row layernorms --------------------
__global__ __launch_bounds__(256) void ln_kernel(
    const float* __restrict__ a, const float* __restrict__ s,
    const float* __restrict__ s_scale)
{
    int row = blockIdx.x;
    int tid = threadIdx.x;
    __shared__ float rs[16];
    // ---- a: 512 elems ----
    const float* ar = a + (size_t)row*CA;
    float x0 = ar[tid], x1 = ar[tid+256];
    float sum = x0+x1, ss = x0*x0 + x1*x1;
    #pragma unroll
    for(int o=16;o;o>>=1){ sum += __shfl_xor_sync(0xffffffffu,sum,o); ss += __shfl_xor_sync(0xffffffffu,ss,o); }
    if((tid&31)==0){ rs[tid>>5]=sum; rs[8+(tid>>5)]=ss; }
    __syncthreads();
    if(tid==0){ float S=0,Q=0; for(int i=0;i<8;i++){S+=rs[i];Q+=rs[8+i];} rs[0]=S; rs[8]=Q; }
    __syncthreads();
    float mean = rs[0]*(1.f/CA);
    float var  = rs[8]*(1.f/CA) - mean*mean;
    float rstd = rsqrtf(var + 1e-5f);
    g_a_ln[(size_t)row*CA + tid]      = (x0-mean)*rstd;
    g_a_ln[(size_t)row*CA + tid+256]  = (x1-mean)*rstd;
    __syncthreads();
    // ---- s: 384 elems ----
    const float* sr = s + (size_t)row*CS;
    float y0 = sr[tid];
    float y1 = (tid < CS-256) ? sr[tid+256] : 0.f;
    sum = y0+y1; ss = y0*y0 + y1*y1;
    #pragma unroll
    for(int o=16;o;o>>=1){ sum += __shfl_xor_sync(0xffffffffu,sum,o); ss += __shfl_xor_sync(0xffffffffu,ss,o); }
    if((tid&31)==0){ rs[tid>>5]=sum; rs[8+(tid>>5)]=ss; }
    __syncthreads();
    if(tid==0){ float S=0,Q=0; for(int i=0;i<8;i++){S+=rs[i];Q+=rs[8+i];} rs[0]=S; rs[8]=Q; }
    __syncthreads();
    mean = rs[0]*(1.f/CS);
    var  = rs[8]*(1.f/CS) - mean*mean;
    rstd = rsqrtf(var + 1e-5f);
    g_s_ln[(size_t)row*CS + tid] = (y0-mean)*rstd*s_scale[tid];
    if(tid < CS-256)
        g_s_ln[(size_t)row*CS + tid+256] = (y1-mean)*rstd*s_scale[tid+256];
}

// -------------------- kernel 2: a_norm + glast (triple GEMM, K=384) --------------------
__global__ __launch_bounds__(256) void anorm_kernel(
    const float* __restrict__ s_raw,
    const float* __restrict__ ada_w_s, const float* __restrict__ ada_b_s,
    const float* __restrict__ ada_w_nb,
    const float* __restrict__ w_last, const float* __restrict__ b_last)
{
    const int K = CS;
    __shared__ __align__(16) float As1[16][68];
    __shared__ __align__(16) float As2[16][68];
    __shared__ __align__(16) float Bs1[16][68];
    __shared__ __align__(16) float Bs2[16][68];
    __shared__ __align__(16) float Bs3[16][68];
    int tid = threadIdx.x;
    int tx = tid & 15, ty = tid >> 4;
    int m0 = blockIdx.y*64, n0 = blockIdx.x*64;
    float c1[4][4]={}, c2[4][4]={}, c3[4][4]={};
    for(int k0=0;k0<K;k0+=16){
        #pragma unroll
        for(int p=0;p<4;p++){
            int e = p*256 + tid;
            int mm = e>>4, kk = e&15;
            As1[kk][mm] = g_s_ln[(size_t)(m0+mm)*K + k0+kk];
            As2[kk][mm] = s_raw[(size_t)(m0+mm)*K + k0+kk];
            Bs1[kk][mm] = ada_w_s [(size_t)(n0+mm)*K + k0+kk];
            Bs2[kk][mm] = ada_w_nb[(size_t)(n0+mm)*K + k0+kk];
            Bs3[kk][mm] = w_last  [(size_t)(n0+mm)*K + k0+kk];
        }
        __syncthreads();
        #pragma unroll
        for(int kk=0;kk<16;kk++){
            float a1[4],a2[4],b1[4],b2[4],b3[4];
            #pragma unroll
            for(int i=0;i<4;i++){ a1[i]=As1[kk][ty*4+i]; a2[i]=As2[kk][ty*4+i]; }
            #pragma unroll
            for(int j=0;j<4;j++){ b1[j]=Bs1[kk][tx*4+j]; b2[j]=Bs2[kk][tx*4+j]; b3[j]=Bs3[kk][tx*4+j]; }
            #pragma unroll
            for(int i=0;i<4;i++)
            #pragma unroll
            for(int j=0;j<4;j++){
                c1[i][j] = fmaf(a1[i],b1[j],c1[i][j]);
                c2[i][j] = fmaf(a1[i],b2[j],c2[i][j]);
                c3[i][j] = fmaf(a2[i],b3[j],c3[i][j]);
            }
        }
        __syncthreads();
    }
    #pragma unroll
    for(int i=0;i<4;i++)
    #pragma unroll
    for(int j=0;j<4;j++){
        int m = m0 + ty*4 + i;
        int n = n0 + tx*4 + j;
        float sg = sigm(c1[i][j] + ada_b_s[n]);
        g_anorm[(size_t)m*CA + n] = sg * g_a_ln[(size_t)m*CA + n] + c2[i][j];
        g_glast[(size_t)m*CA + n] = sigm(c3[i][j] + b_last[n]);
    }
}

// -------------------- kernel 3: QKVG projections (virtual N=2048, K=512) --------------------
__global__ __launch_bounds__(256) void qkvg_kernel(
    const float* __restrict__ wq, const float* __restrict__ bq,
    const float* __restrict__ wk, const float* __restrict__ bk,
    const float* __restrict__ wv, const float* __restrict__ bv,
    const float* __restrict__ wg, const float* __restrict__ bg)
{
    const int K = CA;
    __shared__ __align__(16) float As[16][132];
    __shared__ __align__(16) float Bs[16][132];
    int tid = threadIdx.x;
    int tx = tid & 15, ty = tid >> 4;
    int m0 = blockIdx.y*128;
    int n0 = blockIdx.x*128;
    int which = n0 >> 9;                 // 0=q,1=k,2=v,3=g (128-tile never straddles)
    int nn0 = n0 & 511;
    const float* W  = (which==0)?wq : (which==1)?wk : (which==2)?wv : wg;
    const float* Bv = (which==0)?bq : (which==1)?bk : (which==2)?bv : bg;
    float c[8][8]={};
    for(int k0=0;k0<K;k0+=16){
        #pragma unroll
        for(int p=0;p<8;p++){
            int e = p*256 + tid;
            int mm = e>>4, kk = e&15;
            As[kk][mm] = g_anorm[(size_t)(m0+mm)*K + k0+kk];
            Bs[kk][mm] = W[(size_t)(nn0+mm)*K + k0+kk];
        }
        __syncthreads();
        #pragma unroll
        for(int kk=0;kk<16;kk++){
            float av[8], bv2[8];
            float4 t;
            t = *(const float4*)&As[kk][ty*8];   av[0]=t.x;av[1]=t.y;av[2]=t.z;av[3]=t.w;
            t = *(const float4*)&As[kk][ty*8+4]; av[4]=t.x;av[5]=t.y;av[6]=t.z;av[7]=t.w;
            t = *(const float4*)&Bs[kk][tx*8];   bv2[0]=t.x;bv2[1]=t.y;bv2[2]=t.z;bv2[3]=t.w;
            t = *(const float4*)&Bs[kk][tx*8+4]; bv2[4]=t.x;bv2[5]=t.y;bv2[6]=t.z;bv2[7]=t.w;
            #pragma unroll
            for(int i=0;i<8;i++)
            #pragma unroll
            for(int j=0;j<8;j++) c[i][j] = fmaf(av[i],bv2[j],c[i][j]);
        }
        __syncthreads();
    }
    float* dst = (which==0)?g_q : (which==1)?g_k : g_v;
    #pragma unroll
    for(int i=0;i<8;i++)
    #pragma unroll
    for(int j=0;j<8;j++){
        int m = m0 + ty*8 + i;
        int nn = nn0 + tx*8 + j;
        float val = c[i][j] + Bv[nn];
        if(which < 3){
            int hh = nn>>5, dd2 = nn&31;
            int bb = m>>10, ll = m&1023;
            dst[(((size_t)(bb*HH+hh))*LL + ll)*DD + dd2] = val;
        } else {
            g_g[(size_t)m*CA + nn] = val;
        }
    }
}

// -------------------- kernel 4: pair bias from z --------------------
// bias[b,h,q,k] = rstd * ( dot(z, scale*wz_h) - mean * sum(scale*wz_h) )
__global__ __launch_bounds__(256) void bias_kernel(
    const float* __restrict__ z, const float* __restrict__ z_scale,
    const float* __restrict__ wz)
{
    __shared__ __align__(16) float wzs[HH*CZ];
    __shared__ float wsum[HH];
    int tid = threadIdx.x;
    for(int e=tid;e<HH*CZ;e+=256) wzs[e] = wz[e]*z_scale[e & (CZ-1)];
    __syncthreads();
    if(tid < HH){ float S=0.f; for(int c=0;c<CZ;c++) S += wzs[tid*CZ+c]; wsum[tid]=S; }
    __syncthreads();

    size_t t = (size_t)blockIdx.x*256 + tid;     // 0 .. 2^21-1
    int b = (int)(t >> 20);
    int q = (int)((t >> 10) & 1023);
    int k = (int)(t & 1023);
    const float* zp = z + t*CZ;
    float zv[CZ];
    float sum=0.f, ssq=0.f;
    #pragma unroll
    for(int c=0;c<CZ;c+=4){
        float4 u = *(const float4*)(zp+c);
        zv[c]=u.x; zv[c+1]=u.y; zv[c+2]=u.z; zv[c+3]=u.w;
        sum += u.x+u.y+u.z+u.w;
        ssq = fmaf(u.x,u.x,fmaf(u.y,u.y,fmaf(u.z,u.z,fmaf(u.w,u.w,ssq))));
    }
    float mean = sum*(1.f/CZ);
    float var  = ssq*(1.f/CZ) - mean*mean;
    float rstd = rsqrtf(var + 1e-5f);
    size_t obase = (((size_t)b*HH)*LL + q)*LL + k;
    #pragma unroll 1
    for(int h=0;h<HH;h++){
        float acc=0.f;
        #pragma unroll
        for(int c=0;c<CZ;c+=4){
            float4 w = *(const float4*)&wzs[h*CZ+c];
            acc = fmaf(zv[c],w.x,fmaf(zv[c+1],w.y,fmaf(zv[c+2],w.z,fmaf(zv[c+3],w.w,acc))));
        }
        g_bias[obase + (size_t)h*LL*LL] = rstd*(acc - mean*wsum[h]);
    }
}

// -------------------- kernel 5: flash attention (fp32, thread-per-q-row) --------------------
__global__ __launch_bounds__(128) void attn_kernel(const int* __restrict__ mask)
{
    int tid = threadIdx.x;        // 128
    int b = blockIdx.z, h = blockIdx.y;
    int q = blockIdx.x*128 + tid;
    const float* qp = g_q + (((size_t)(b*HH+h))*LL + q)*DD;
    float qr[DD];
    #pragma unroll
    for(int d=0;d<DD;d+=4){
        float4 t4 = *(const float4*)(qp+d);
        qr[d]=t4.x*SCALE; qr[d+1]=t4.y*SCALE; qr[d+2]=t4.z*SCALE; qr[d+3]=t4.w*SCALE;
    }
    float O[DD];
    #pragma unroll
    for(int d=0;d<DD;d++) O[d]=0.f;
    float mrun=-1e30f, lrun=0.f;

    __shared__ __align__(16) float Ks[64*DD];
    __shared__ __align__(16) float Vs[64*DD];
    __shared__ float mk[64];
    const float* Kbase = g_k + ((size_t)(b*HH+h))*LL*DD;
    const float* Vbase = g_v + ((size_t)(b*HH+h))*LL*DD;
    const float* brow  = g_bias + (((size_t)(b*HH+h))*LL + q)*LL;

    for(int kt=0; kt<LL; kt+=64){
        __syncthreads();
        #pragma unroll
        for(int p=0;p<4;p++){
            int f = p*128 + tid;  // 0..511 float4s
            ((float4*)Ks)[f] = ((const float4*)(Kbase + (size_t)kt*DD))[f];
            ((float4*)Vs)[f] = ((const float4*)(Vbase + (size_t)kt*DD))[f];
        }
        if(tid < 64) mk[tid] = mask[b*LL + kt + tid] ? 0.f : -2e30f;
        __syncthreads();

        for(int j0=0;j0<64;j0+=4){
            float4 bj = *(const float4*)(brow + kt + j0);
            float bja[4] = {bj.x, bj.y, bj.z, bj.w};
            #pragma unroll
            for(int jj=0;jj<4;jj++){
                int j = j0 + jj;
                const float* kj = Ks + j*DD;
                float s_ = 0.f;
                #pragma unroll
                for(int d=0;d<DD;d+=4){
                    float4 kv = *(const float4*)(kj+d);
                    s_ = fmaf(qr[d],kv.x,fmaf(qr[d+1],kv.y,fmaf(qr[d+2],kv.z,fmaf(qr[d+3],kv.w,s_))));
                }
                s_ += bja[jj] + mk[j];
                const float* vj = Vs + j*DD;
                if(s_ > mrun){
                    float corr = __expf(mrun - s_);
                    mrun = s_;
                    lrun = fmaf(lrun, corr, 1.f);
                    #pragma unroll
                    for(int d=0;d<DD;d+=4){
                        float4 vv = *(const float4*)(vj+d);
                        O[d]  = fmaf(O[d],  corr, vv.x);
                        O[d+1]= fmaf(O[d+1],corr, vv.y);
                        O[d+2]= fmaf(O[d+2],corr, vv.z);
                        O[d+3]= fmaf(O[d+3],corr, vv.w);
                    }
                } else {
                    float p_ = __expf(s_ - mrun);
                    lrun += p_;
                    #pragma unroll
                    for(int d=0;d<DD;d+=4){
                        float4 vv = *(const float4*)(vj+d);
                        O[d]  = fmaf(p_,vv.x,O[d]);
                        O[d+1]= fmaf(p_,vv.y,O[d+1]);
                        O[d+2]= fmaf(p_,vv.z,O[d+2]);
                        O[d+3]= fmaf(p_,vv.w,O[d+3]);
                    }
                }
            }
        }
    }
    float inv = 1.f/fmaxf(lrun, 1e-20f);
    float* dst = g_ao + ((size_t)(b*LL + q))*CA + h*DD;
    #pragma unroll
    for(int d=0;d<DD;d+=4){
        float4 o4 = make_float4(O[d]*inv, O[d+1]*inv, O[d+2]*inv, O[d+3]*inv);
        *(float4*)(dst+d) = o4;
    }
}

// -------------------- kernel 6: out = (sigmoid(g)*ao)@wo^T + bo, gated, masked ----------
__global__ __launch_bounds__(256) void out_kernel(
    const float* __restrict__ wo, const float* __restrict__ bo,
    const int* __restrict__ mask, float* __restrict__ out)
{
    const int K = CA;
    __shared__ __align__(16) float As[16][68];
    __shared__ __align__(16) float Bs[16][68];
    int tid = threadIdx.x;
    int tx = tid & 15, ty = tid >> 4;
    int m0 = blockIdx.y*64, n0 = blockIdx.x*64;
    float c[4][4]={};
    for(int k0=0;k0<K;k0+=16){
        #pragma unroll
        for(int p=0;p<4;p++){
            int e = p*256 + tid;
            int mm = e>>4, kk = e&15;
            size_t ai = (size_t)(m0+mm)*K + k0+kk;
            As[kk][mm] = sigm(g_g[ai]) * g_ao[ai];
            Bs[kk][mm] = wo[(size_t)(n0+mm)*K + k0+kk];
        }
        __syncthreads();
        #pragma unroll
        for(int kk=0;kk<16;kk++){
            float av[4], bv2[4];
            #pragma unroll
            for(int i=0;i<4;i++) av[i]=As[kk][ty*4+i];
            #pragma unroll
            for(int j=0;j<4;j++) bv2[j]=Bs[kk][tx*4+j];
            #pragma unroll
            for(int i=0;i<4;i++)
            #pragma unroll
            for(int j=0;j<4;j++) c[i][j] = fmaf(av[i],bv2[j],c[i][j]);
        }
        __syncthreads();
    }
    #pragma unroll
    for(int i=0;i<4;i++){
        int m = m0 + ty*4 + i;
        float mq = mask[m] ? 1.f : 0.f;
        #pragma unroll
        for(int j=0;j<4;j++){
            int n = n0 + tx*4 + j;
            out[(size_t)m*CA + n] = (c[i][j] + bo[n]) * g_glast[(size_t)m*CA + n] * mq;
        }
    }
}

// -------------------- launch --------------------
extern "C" void kernel_launch(void* const* d_in, const int* in_sizes, int n_in,
                              void* d_out, int out_size)
{
    const float* a          = (const float*)d_in[0];
    const float* s          = (const float*)d_in[1];
    const float* z          = (const float*)d_in[2];
    const float* ln_s_scale = (const float*)d_in[3];
    const float* ada_w_s    = (const float*)d_in[4];
    const float* ada_b_s    = (const float*)d_in[5];
    const float* ada_w_nb   = (const float*)d_in[6];
    const float* wq = (const float*)d_in[7];  const float* bq = (const float*)d_in[8];
    const float* wk = (const float*)d_in[9];  const float* bk = (const float*)d_in[10];
    const float* wv = (const float*)d_in[11]; const float* bv = (const float*)d_in[12];
    const float* wg = (const float*)d_in[13]; const float* bg = (const float*)d_in[14];
    const float* wo = (const float*)d_in[15]; const float* bo = (const float*)d_in[16];
    const float* ln_z_scale = (const float*)d_in[17];
    const float* wz         = (const float*)d_in[18];
    const float* w_last     = (const float*)d_in[19];
    const float* b_last     = (const float*)d_in[20];
    const int*   mask       = (const int*)d_in[21];
    float* out = (float*)d_out;

    ln_kernel<<<MM, 256>>>(a, s, ln_s_scale);
    anorm_kernel<<<dim3(CA/64, MM/64), 256>>>(s, ada_w_s, ada_b_s, ada_w_nb, w_last, b_last);
    qkvg_kernel<<<dim3(2048/128, MM/128), 256>>>(wq,bq, wk,bk, wv,bv, wg,bg);
    bias_kernel<<<(BB*LL*LL)/256, 256>>>(z, ln_z_scale, wz);
    attn_kernel<<<dim3(LL/128, HH, BB), 128>>>(mask);
    out_kernel<<<dim3(CA/64, MM/64), 256>>>(wo, bo, mask, out);
}

// round 3
// speedup vs baseline: 1.2063x; 1.2063x over previous
#include <cuda_runtime.h>
#include <cuda_bf16.h>
#include <cuda_fp16.h>

// Problem constants
#define BB 2
#define LL 1024
#define CA 512
#define CS 384
#define CZ 64
#define HH 16
#define DD 32
#define MM (BB*LL)          // 2048 rows
#define SCALE 0.17677669529663687f  // 1/sqrt(32)

typedef unsigned long long U64;
__device__ __forceinline__ U64 pk2(float lo, float hi){ U64 r; asm("mov.b64 %0, {%1,%2};":"=l"(r):"f"(lo),"f"(hi)); return r; }
__device__ __forceinline__ void fma2(U64 &d, U64 a, U64 b){ asm("fma.rn.f32x2 %0, %1, %2, %3;":"=l"(d):"l"(a),"l"(b),"l"(d)); }
__device__ __forceinline__ float2 up2(U64 v){ float2 r; asm("mov.b64 {%0,%1}, %2;":"=f"(r.x),"=f"(r.y):"l"(v)); return r; }

// -------------------- device scratch --------------------
__device__ __align__(16) float g_s_ln[MM*CS];
__device__ __align__(16) float g_a_ln[MM*CA];
__device__ __align__(16) float g_anorm[MM*CA];
__device__ __align__(16) float g_glast[MM*CA];
__device__ __align__(16) float g_q[MM*CA];   // [b][h][l][d]
__device__ __align__(16) float g_k[MM*CA];
__device__ __align__(16) float g_v[MM*CA];
__device__ __align__(16) float g_g[MM*CA];   // pre-sigmoid gate
__device__ __align__(16) float g_ao[MM*CA];  // attention out [b][l][h*32+d]
__device__ __align__(16) __half g_biash[(size_t)BB*HH*LL*LL]; // 67MB fp16 bias

__device__ __forceinline__ float sigm(float x){ return 1.f/(1.f+__expf(-x)); }

// -------------------- kernel 1: row layernorms --------------------
__global__ __launch_bounds__(256) void ln_kernel(
    const float* __restrict__ a, const float* __restrict__ s,
    const float* __restrict__ s_scale)
{
    int row = blockIdx.x;
    int tid = threadIdx.x;
    __shared__ float rs[16];
    const float* ar = a + (size_t)row*CA;
    float x0 = ar[tid], x1 = ar[tid+256];
    float sum = x0+x1, ss = x0*x0 + x1*x1;
    #pragma unroll
    for(int o=16;o;o>>=1){ sum += __shfl_xor_sync(0xffffffffu,sum,o); ss += __shfl_xor_sync(0xffffffffu,ss,o); }
    if((tid&31)==0){ rs[tid>>5]=sum; rs[8+(tid>>5)]=ss; }
    __syncthreads();
    if(tid==0){ float S=0,Q=0; for(int i=0;i<8;i++){S+=rs[i];Q+=rs[8+i];} rs[0]=S; rs[8]=Q; }
    __syncthreads();
    float mean = rs[0]*(1.f/CA);
    float var  = rs[8]*(1.f/CA) - mean*mean;
    float rstd = rsqrtf(var + 1e-5f);
    g_a_ln[(size_t)row*CA + tid]      = (x0-mean)*rstd;
    g_a_ln[(size_t)row*CA + tid+256]  = (x1-mean)*rstd;
    __syncthreads();
    const float* sr = s + (size_t)row*CS;
    float y0 = sr[tid];
    float y1 = (tid < CS-256) ? sr[tid+256] : 0.f;
    sum = y0+y1; ss = y0*y0 + y1*y1;
    #pragma unroll
    for(int o=16;o;o>>=1){ sum += __shfl_xor_sync(0xffffffffu,sum,o); ss += __shfl_xor_sync(0xffffffffu,ss,o); }
    if((tid&31)==0){ rs[tid>>5]=sum; rs[8+(tid>>5)]=ss; }
    __syncthreads();
    if(tid==0){ float S=0,Q=0; for(int i=0;i<8;i++){S+=rs[i];Q+=rs[8+i];} rs[0]=S; rs[8]=Q; }
    __syncthreads();
    mean = rs[0]*(1.f/CS);
    var  = rs[8]*(1.f/CS) - mean*mean;
    rstd = rsqrtf(var + 1e-5f);
    g_s_ln[(size_t)row*CS + tid] = (y0-mean)*rstd*s_scale[tid];
    if(tid < CS-256)
        g_s_ln[(size_t)row*CS + tid+256] = (y1-mean)*rstd*s_scale[tid+256];
}

// -------------------- kernel 2: a_norm + glast (triple GEMM, f32x2) --------------------
__global__ __launch_bounds__(256) void anorm_kernel(
    const float* __restrict__ s_raw,
    const float* __restrict__ ada_w_s, const float* __restrict__ ada_b_s,
    const float* __restrict__ ada_w_nb,
    const float* __restrict__ w_last, const float* __restrict__ b_last)
{
    const int K = CS;
    __shared__ __align__(16) float As1[16][72];
    __shared__ __align__(16) float As2[16][72];
    __shared__ __align__(16) float Bs1[16][72];
    __shared__ __align__(16) float Bs2[16][72];
    __shared__ __align__(16) float Bs3[16][72];
    int tid = threadIdx.x;
    int tx = tid & 15, ty = tid >> 4;
    int m0 = blockIdx.y*64, n0 = blockIdx.x*64;
    U64 c1[4][2]={}, c2[4][2]={}, c3[4][2]={};
    for(int k0=0;k0<K;k0+=16){
        #pragma unroll
        for(int p=0;p<4;p++){
            int e = p*256 + tid;
            int mm = e>>4, kk = e&15;
            As1[kk][mm] = g_s_ln[(size_t)(m0+mm)*K + k0+kk];
            As2[kk][mm] = s_raw[(size_t)(m0+mm)*K + k0+kk];
            Bs1[kk][mm] = ada_w_s [(size_t)(n0+mm)*K + k0+kk];
            Bs2[kk][mm] = ada_w_nb[(size_t)(n0+mm)*K + k0+kk];
            Bs3[kk][mm] = w_last  [(size_t)(n0+mm)*K + k0+kk];
        }
        __syncthreads();
        #pragma unroll
        for(int kk=0;kk<16;kk++){
            float4 a1 = *(const float4*)&As1[kk][ty*4];
            float4 a2 = *(const float4*)&As2[kk][ty*4];
            ulonglong2 b1 = *(const ulonglong2*)&Bs1[kk][tx*4];
            ulonglong2 b2 = *(const ulonglong2*)&Bs2[kk][tx*4];
            ulonglong2 b3 = *(const ulonglong2*)&Bs3[kk][tx*4];
            U64 a1d[4], a2d[4];
            a1d[0]=pk2(a1.x,a1.x); a1d[1]=pk2(a1.y,a1.y); a1d[2]=pk2(a1.z,a1.z); a1d[3]=pk2(a1.w,a1.w);
            a2d[0]=pk2(a2.x,a2.x); a2d[1]=pk2(a2.y,a2.y); a2d[2]=pk2(a2.z,a2.z); a2d[3]=pk2(a2.w,a2.w);
            #pragma unroll
            for(int i=0;i<4;i++){
                fma2(c1[i][0],a1d[i],b1.x); fma2(c1[i][1],a1d[i],b1.y);
                fma2(c2[i][0],a1d[i],b2.x); fma2(c2[i][1],a1d[i],b2.y);
                fma2(c3[i][0],a2d[i],b3.x); fma2(c3[i][1],a2d[i],b3.y);
            }
        }
        __syncthreads();
    }
    #pragma unroll
    for(int i=0;i<4;i++){
        int m = m0 + ty*4 + i;
        #pragma unroll
        for(int jp=0;jp<2;jp++){
            float2 v1 = up2(c1[i][jp]), v2 = up2(c2[i][jp]), v3 = up2(c3[i][jp]);
            int n = n0 + tx*4 + jp*2;
            float sgA = sigm(v1.x + ada_b_s[n]);
            float sgB = sigm(v1.y + ada_b_s[n+1]);
            g_anorm[(size_t)m*CA + n]   = sgA * g_a_ln[(size_t)m*CA + n]   + v2.x;
            g_anorm[(size_t)m*CA + n+1] = sgB * g_a_ln[(size_t)m*CA + n+1] + v2.y;
            g_glast[(size_t)m*CA + n]   = sigm(v3.x + b_last[n]);
            g_glast[(size_t)m*CA + n+1] = sigm(v3.y + b_last[n+1]);
        }
    }
}

// -------------------- kernel 3: QKVG projections (f32x2) --------------------
__global__ __launch_bounds__(256) void qkvg_kernel(
    const float* __restrict__ wq, const float* __restrict__ bq,
    const float* __restrict__ wk, const float* __restrict__ bk,
    const float* __restrict__ wv, const float* __restrict__ bv,
    const float* __restrict__ wg, const float* __restrict__ bg)
{
    const int K = CA;
    __shared__ __align__(16) float As[16][136];
    __shared__ __align__(16) float Bs[16][136];
    int tid = threadIdx.x;
    int tx = tid & 15, ty = tid >> 4;
    int m0 = blockIdx.y*128;
    int n0 = blockIdx.x*128;
    int which = n0 >> 9;
    int nn0 = n0 & 511;
    const float* W  = (which==0)?wq : (which==1)?wk : (which==2)?wv : wg;
    const float* Bv = (which==0)?bq : (which==1)?bk : (which==2)?bv : bg;
    U64 c[8][4]={};
    for(int k0=0;k0<K;k0+=16){
        #pragma unroll
        for(int p=0;p<8;p++){
            int e = p*256 + tid;
            int mm = e>>4, kk = e&15;
            As[kk][mm] = g_anorm[(size_t)(m0+mm)*K + k0+kk];
            Bs[kk][mm] = W[(size_t)(nn0+mm)*K + k0+kk];
        }
        __syncthreads();
        #pragma unroll
        for(int kk=0;kk<16;kk++){
            float4 t0 = *(const float4*)&As[kk][ty*8];
            float4 t1 = *(const float4*)&As[kk][ty*8+4];
            ulonglong2 b0 = *(const ulonglong2*)&Bs[kk][tx*8];
            ulonglong2 b1 = *(const ulonglong2*)&Bs[kk][tx*8+4];
            U64 ad[8];
            ad[0]=pk2(t0.x,t0.x); ad[1]=pk2(t0.y,t0.y); ad[2]=pk2(t0.z,t0.z); ad[3]=pk2(t0.w,t0.w);
            ad[4]=pk2(t1.x,t1.x); ad[5]=pk2(t1.y,t1.y); ad[6]=pk2(t1.z,t1.z); ad[7]=pk2(t1.w,t1.w);
            #pragma unroll
            for(int i=0;i<8;i++){
                fma2(c[i][0],ad[i],b0.x); fma2(c[i][1],ad[i],b0.y);
                fma2(c[i][2],ad[i],b1.x); fma2(c[i][3],ad[i],b1.y);
            }
        }
        __syncthreads();
    }
    float* dst = (which==0)?g_q : (which==1)?g_k : g_v;
    #pragma unroll
    for(int i=0;i<8;i++){
        int m = m0 + ty*8 + i;
        #pragma unroll
        for(int jp=0;jp<4;jp++){
            float2 v = up2(c[i][jp]);
            #pragma unroll
            for(int l=0;l<2;l++){
                int nn = nn0 + tx*8 + jp*2 + l;
                float val = (l?v.y:v.x) + Bv[nn];
                if(which < 3){
                    int hh = nn>>5, dd2 = nn&31;
                    int bb = m>>10, ll = m&1023;
                    dst[(((size_t)(bb*HH+hh))*LL + ll)*DD + dd2] = val;
                } else {
                    g_g[(size_t)m*CA + nn] = val;
                }
            }
        }
    }
}

// -------------------- kernel 4: pair bias (f32x2, fp16 out, 2 pairs/thread) --------------------
__global__ __launch_bounds__(256) void bias_kernel(
    const float* __restrict__ z, const float* __restrict__ z_scale,
    const float* __restrict__ wz)
{
    __shared__ __align__(16) float wzs[HH][CZ];
    __shared__ float wsum[HH];
    int tid = threadIdx.x;
    for(int e=tid;e<HH*CZ;e+=256) wzs[e>>6][e&63] = wz[e]*z_scale[e&63];
    __syncthreads();
    if(tid < HH){ float S=0.f; for(int c=0;c<CZ;c++) S += wzs[tid][c]; wsum[tid]=S; }
    __syncthreads();

    size_t t0 = (size_t)blockIdx.x*512 + tid;      // first pair
    size_t t1 = t0 + 256;                          // second pair (coalesced warps)
    const ulonglong2* zp0 = (const ulonglong2*)(z + t0*CZ);
    const ulonglong2* zp1 = (const ulonglong2*)(z + t1*CZ);

    U64 acc0[HH], acc1[HH];
    #pragma unroll
    for(int h=0;h<HH;h++){ acc0[h]=0ull; acc1[h]=0ull; }
    U64 sum0=0ull, ssq0=0ull, sum1=0ull, ssq1=0ull;
    const U64 one2 = pk2(1.f,1.f);

    #pragma unroll
    for(int cs=0;cs<16;cs++){
        ulonglong2 z0 = zp0[cs];
        ulonglong2 z1 = zp1[cs];
        fma2(sum0,z0.x,one2); fma2(sum0,z0.y,one2);
        fma2(ssq0,z0.x,z0.x); fma2(ssq0,z0.y,z0.y);
        fma2(sum1,z1.x,one2); fma2(sum1,z1.y,one2);
        fma2(ssq1,z1.x,z1.x); fma2(ssq1,z1.y,z1.y);
        #pragma unroll
        for(int h=0;h<HH;h++){
            ulonglong2 w = *(const ulonglong2*)&wzs[h][cs*4];
            fma2(acc0[h],z0.x,w.x); fma2(acc0[h],z0.y,w.y);
            fma2(acc1[h],z1.x,w.x); fma2(acc1[h],z1.y,w.y);
        }
    }
    float2 s0=up2(sum0), q0=up2(ssq0), s1=up2(sum1), q1=up2(ssq1);
    float mean0=(s0.x+s0.y)*(1.f/CZ), mean1=(s1.x+s1.y)*(1.f/CZ);
    float rstd0=rsqrtf((q0.x+q0.y)*(1.f/CZ)-mean0*mean0+1e-5f);
    float rstd1=rsqrtf((q1.x+q1.y)*(1.f/CZ)-mean1*mean1+1e-5f);

    // t = b*2^20 + q*2^10 + k; bias[b,h,q,k]
    int b0_ = (int)(t0>>20), q0_ = (int)((t0>>10)&1023), k0_ = (int)(t0&1023);
    int b1_ = (int)(t1>>20), q1_ = (int)((t1>>10)&1023), k1_ = (int)(t1&1023);
    size_t ob0 = (((size_t)b0_*HH)*LL + q0_)*LL + k0_;
    size_t ob1 = (((size_t)b1_*HH)*LL + q1_)*LL + k1_;
    #pragma unroll
    for(int h=0;h<HH;h++){
        float2 d0 = up2(acc0[h]);
        float2 d1 = up2(acc1[h]);
        g_biash[ob0 + (size_t)h*LL*LL] = __float2half(rstd0*((d0.x+d0.y) - mean0*wsum[h]));
        g_biash[ob1 + (size_t)h*LL*LL] = __float2half(rstd1*((d1.x+d1.y) - mean1*wsum[h]));
    }
}

// -------------------- kernel 5: attention (branchless softmax, 2 lanes/row, f32x2) ----
__global__ __launch_bounds__(128) void attn_kernel(const int* __restrict__ mask)
{
    __shared__ __align__(16) float Ks[64*32];
    __shared__ __align__(16) float Vs[64*32];
    __shared__ __align__(16) __half bsh[64][80];
    __shared__ float mk[64];

    int tid = threadIdx.x;          // 128
    int b = blockIdx.z, h = blockIdx.y;
    int q0 = blockIdx.x*64;
    int row = tid >> 1;             // 0..63
    int half = tid & 1;             // which 16-d half

    const float* qp = g_q + (((size_t)(b*HH+h))*LL + q0+row)*DD + half*16;
    U64 qr2[8];
    #pragma unroll
    for(int i=0;i<4;i++){
        float4 t4 = ((const float4*)qp)[i];
        qr2[i*2]   = pk2(t4.x*SCALE, t4.y*SCALE);
        qr2[i*2+1] = pk2(t4.z*SCALE, t4.w*SCALE);
    }
    U64 O2[8];
    #pragma unroll
    for(int i=0;i<8;i++) O2[i]=0ull;
    float lrun = 0.f;

    const float* Kbase = g_k + ((size_t)(b*HH+h))*LL*DD;
    const float* Vbase = g_v + ((size_t)(b*HH+h))*LL*DD;
    const __half* bbase = g_biash + (((size_t)(b*HH+h))*LL + q0)*LL;

    for(int kt=0; kt<LL; kt+=64){
        __syncthreads();
        #pragma unroll
        for(int p=0;p<4;p++){
            int f = p*128 + tid;  // 512 float4s
            ((float4*)Ks)[f] = ((const float4*)(Kbase + (size_t)kt*DD))[f];
            ((float4*)Vs)[f] = ((const float4*)(Vbase + (size_t)kt*DD))[f];
        }
        #pragma unroll
        for(int p=0;p<4;p++){
            int c = p*128 + tid;   // 512 chunks of 8 halves
            int r = c>>3, part = c&7;
            *(float4*)&bsh[r][part*8] = ((const float4*)(bbase + (size_t)r*LL + kt))[part];
        }
        if(tid < 64) mk[tid] = mask[b*LL + kt + tid] ? 0.f : -10000.f;
        __syncthreads();

        #pragma unroll 2
        for(int j0=0;j0<64;j0+=4){
            const __half2* bp = (const __half2*)&bsh[row][j0];
            float2 b01 = __half22float2(bp[0]);
            float2 b23 = __half22float2(bp[1]);
            float bb4[4] = {b01.x, b01.y, b23.x, b23.y};
            #pragma unroll
            for(int jj=0;jj<4;jj++){
                int j = j0 + jj;
                const ulonglong2* kp = (const ulonglong2*)&Ks[j*32 + half*16];
                U64 sacc = 0ull;
                #pragma unroll
                for(int i=0;i<4;i++){
                    ulonglong2 kv = kp[i];
                    fma2(sacc, qr2[i*2],   kv.x);
                    fma2(sacc, qr2[i*2+1], kv.y);
                }
                float2 sp = up2(sacc);
                float part = sp.x + sp.y;
                float tot = part + __shfl_xor_sync(0xffffffffu, part, 1);
                float s_ = tot + bb4[jj] + mk[j];
                float p_ = __expf(s_);
                lrun += p_;
                U64 pp = pk2(p_, p_);
                const ulonglong2* vp = (const ulonglong2*)&Vs[j*32 + half*16];
                #pragma unroll
                for(int i=0;i<4;i++){
                    ulonglong2 vv = vp[i];
                    fma2(O2[i*2],   pp, vv.x);
                    fma2(O2[i*2+1], pp, vv.y);
                }
            }
        }
    }
    float inv = 1.f/fmaxf(lrun, 1e-20f);
    float* dst = g_ao + ((size_t)(b*LL + q0+row))*CA + h*DD + half*16;
    #pragma unroll
    for(int i=0;i<4;i++){
        float2 v0 = up2(O2[i*2]), v1 = up2(O2[i*2+1]);
        ((float4*)dst)[i] = make_float4(v0.x*inv, v0.y*inv, v1.x*inv, v1.y*inv);
    }
}

// -------------------- kernel 6: output GEMM (f32x2) --------------------
__global__ __launch_bounds__(256) void out_kernel(
    const float* __restrict__ wo, const float* __restrict__ bo,
    const int* __restrict__ mask, float* __restrict__ out)
{
    const int K = CA;
    __shared__ __align__(16) float As[16][72];
    __shared__ __align__(16) float Bs[16][72];
    int tid = threadIdx.x;
    int tx = tid & 15, ty = tid >> 4;
    int m0 = blockIdx.y*64, n0 = blockIdx.x*64;
    U64 c[4][2]={};
    for(int k0=0;k0<K;k0+=16){
        #pragma unroll
        for(int p=0;p<4;p++){
            int e = p*256 + tid;
            int mm = e>>4, kk = e&15;
            size_t ai = (size_t)(m0+mm)*K + k0+kk;
            As[kk][mm] = sigm(g_g[ai]) * g_ao[ai];
            Bs[kk][mm] = wo[(size_t)(n0+mm)*K + k0+kk];
        }
        __syncthreads();
        #pragma unroll
        for(int kk=0;kk<16;kk++){
            float4 a4 = *(const float4*)&As[kk][ty*4];
            ulonglong2 bu = *(const ulonglong2*)&Bs[kk][tx*4];
            U64 ad[4];
            ad[0]=pk2(a4.x,a4.x); ad[1]=pk2(a4.y,a4.y); ad[2]=pk2(a4.z,a4.z); ad[3]=pk2(a4.w,a4.w);
            #pragma unroll
            for(int i=0;i<4;i++){
                fma2(c[i][0],ad[i],bu.x);
                fma2(c[i][1],ad[i],bu.y);
            }
        }
        __syncthreads();
    }
    #pragma unroll
    for(int i=0;i<4;i++){
        int m = m0 + ty*4 + i;
        float mq = mask[m] ? 1.f : 0.f;
        #pragma unroll
        for(int jp=0;jp<2;jp++){
            float2 v = up2(c[i][jp]);
            int n = n0 + tx*4 + jp*2;
            out[(size_t)m*CA + n]   = (v.x + bo[n])   * g_glast[(size_t)m*CA + n]   * mq;
            out[(size_t)m*CA + n+1] = (v.y + bo[n+1]) * g_glast[(size_t)m*CA + n+1] * mq;
        }
    }
}

// -------------------- launch --------------------
extern "C" void kernel_launch(void* const* d_in, const int* in_sizes, int n_in,
                              void* d_out, int out_size)
{
    const float* a          = (const float*)d_in[0];
    const float* s          = (const float*)d_in[1];
    const float* z          = (const float*)d_in[2];
    const float* ln_s_scale = (const float*)d_in[3];
    const float* ada_w_s    = (const float*)d_in[4];
    const float* ada_b_s    = (const float*)d_in[5];
    const float* ada_w_nb   = (const float*)d_in[6];
    const float* wq = (const float*)d_in[7];  const float* bq = (const float*)d_in[8];
    const float* wk = (const float*)d_in[9];  const float* bk = (const float*)d_in[10];
    const float* wv = (const float*)d_in[11]; const float* bv = (const float*)d_in[12];
    const float* wg = (const float*)d_in[13]; const float* bg = (const float*)d_in[14];
    const float* wo = (const float*)d_in[15]; const float* bo = (const float*)d_in[16];
    const float* ln_z_scale = (const float*)d_in[17];
    const float* wz         = (const float*)d_in[18];
    const float* w_last     = (const float*)d_in[19];
    const float* b_last     = (const float*)d_in[20];
    const int*   mask       = (const int*)d_in[21];
    float* out = (float*)d_out;

    ln_kernel<<<MM, 256>>>(a, s, ln_s_scale);
    anorm_kernel<<<dim3(CA/64, MM/64), 256>>>(s, ada_w_s, ada_b_s, ada_w_nb, w_last, b_last);
    qkvg_kernel<<<dim3(2048/128, MM/128), 256>>>(wq,bq, wk,bk, wv,bv, wg,bg);
    bias_kernel<<<(BB*LL*LL)/512, 256>>>(z, ln_z_scale, wz);
    attn_kernel<<<dim3(LL/64, HH, BB), 128>>>(mask);
    out_kernel<<<dim3(CA/64, MM/64), 256>>>(wo, bo, mask, out);
}